// round 15
// baseline (speedup 1.0000x reference)
#include <cuda_runtime.h>
#include <cuda_fp16.h>
#include <stdint.h>
#include <string.h>

#define N_LEVELS 16
#define BATCH (1 << 20)
#define DENSE_TOTAL 1023633          // sum of res^3 for levels 0..7 (== OFFSETS[8])
#define HASHED_BASE 1023633          // first hashed entry
#define HQUADS 1048576               // (5217937 - 1023633) / 4 quads

// full 2x2x2 corner cube per dense cell, fp16: 8 corners x half2 = 32 bytes
struct __align__(32) Cube { uint32_t h[8]; };   // h[c] = half2(f0,f1), c = (cx<<2)|(cy<<1)|cz
__device__ Cube g_cube[DENSE_TOTAL];
// hashed quad table, fp16: g_hquad[m] = entries {4m,4m+1,4m+2,4m+3} as half2 each
__device__ uint4 g_hquad[HQUADS];

__host__ __device__ __forceinline__ constexpr int lvl_res(int l) {
    constexpr int r[N_LEVELS] = {16, 20, 25, 32, 40, 50, 64, 80, 101, 128, 161, 203, 256, 322, 406, 512};
    return r[l];
}
__host__ __device__ __forceinline__ constexpr int lvl_off(int l) {
    constexpr int o[N_LEVELS + 1] = {0, 4096, 12096, 27721, 60489, 124489, 249489, 511633, 1023633,
                                     1547921, 2072209, 2596497, 3120785, 3645073, 4169361, 4693649, 5217937};
    return o[l];
}

// bit-casts (compile to nothing)
__device__ __forceinline__ uint32_t h2_to_u32(__half2 h) {
    uint32_t u; memcpy(&u, &h, 4); return u;
}
__device__ __forceinline__ float2 u32_to_f2(uint32_t u) {
    __half2 h; memcpy(&h, &u, 4); return __half22float2(h);
}
// select one of 4 packed half2 words by index s (2-level SEL chain, no local mem)
__device__ __forceinline__ uint32_t sel4(uint4 q, uint32_t s) {
    const uint32_t a = (s & 1u) ? q.y : q.x;
    const uint32_t b = (s & 1u) ? q.w : q.z;
    return (s & 2u) ? b : a;
}

// plain 256-bit global loads (sm_100+)
struct U8 { uint32_t v[8]; };
__device__ __forceinline__ U8 ldg256u(const Cube* p) {
    U8 q;
    asm("ld.global.nc.v8.b32 {%0,%1,%2,%3,%4,%5,%6,%7}, [%8];"
        : "=r"(q.v[0]), "=r"(q.v[1]), "=r"(q.v[2]), "=r"(q.v[3]),
          "=r"(q.v[4]), "=r"(q.v[5]), "=r"(q.v[6]), "=r"(q.v[7])
        : "l"(p));
    return q;
}
// plain 256-bit store
__device__ __forceinline__ void stg256(float* p, const float* v) {
    asm volatile("st.global.v8.f32 [%0], {%1,%2,%3,%4,%5,%6,%7,%8};"
        :: "l"(p), "f"(v[0]), "f"(v[1]), "f"(v[2]), "f"(v[3]),
           "f"(v[4]), "f"(v[5]), "f"(v[6]), "f"(v[7]) : "memory");
}

// ── prologue: build fp16 cube table + fp16 hashed quad table in one launch ─
#define REPACK_ITEMS (DENSE_TOTAL + HQUADS)
__global__ __launch_bounds__(256) void repack_all(const float2* __restrict__ emb)
{
    for (int t = blockIdx.x * blockDim.x + threadIdx.x; t < REPACK_ITEMS;
         t += gridDim.x * blockDim.x) {
        if (t < DENSE_TOTAL) {
            const int i = t;
            int res = 0;
#pragma unroll
            for (int l = 0; l < 8; ++l)
                if (i >= lvl_off(l) && i < lvl_off(l + 1)) res = lvl_res(l);
            const int r2 = res * res;
            Cube cu;
#pragma unroll
            for (int c = 0; c < 8; ++c) {
                const int dx = (c >> 2) & 1, dy = (c >> 1) & 1, dz = c & 1;
                // edge cells read garbage neighbors but stay inside emb; never consumed.
                const float2 v = __ldg(emb + i + dx * r2 + dy * res + dz);
                cu.h[c] = h2_to_u32(__floats2half2_rn(v.x, v.y));
            }
            g_cube[i] = cu;
        } else {
            const int m = t - DENSE_TOTAL;
            const float2* p = emb + HASHED_BASE + 4 * m;
            uint4 q;
            q.x = h2_to_u32(__floats2half2_rn(p[0].x, p[0].y));
            q.y = h2_to_u32(__floats2half2_rn(p[1].x, p[1].y));
            q.z = h2_to_u32(__floats2half2_rn(p[2].x, p[2].y));
            q.w = h2_to_u32(__floats2half2_rn(p[3].x, p[3].y));
            g_hquad[m] = q;
        }
    }
}

// ── fused main kernel: all 16 levels per point ─────────────────────────────
__global__ __launch_bounds__(256, 6) void hashgrid_kernel(
    const float* __restrict__ xyz,
    const float* __restrict__ mn,
    const float* __restrict__ mx,
    float* __restrict__ out)
{
    const int b = blockIdx.x * blockDim.x + threadIdx.x;   // grid*block == BATCH exactly

    const float inv_x = 1.0f / (mx[0] - mn[0]);
    const float inv_y = 1.0f / (mx[1] - mn[1]);
    const float inv_z = 1.0f / (mx[2] - mn[2]);
    const float xn = (xyz[3 * b + 0] - mn[0]) * inv_x;
    const float yn = (xyz[3 * b + 1] - mn[1]) * inv_y;
    const float zn = (xyz[3 * b + 2] - mn[2]) * inv_z;

    float* obase = out + (size_t)b * (2 * N_LEVELS);
    float buf[8];   // 4 levels x 2 feats, flushed via one STG.256

#pragma unroll
    for (int l = 0; l < N_LEVELS; ++l) {
        const int res = lvl_res(l);
        const int off = lvl_off(l);

        const float sc = (float)(res - 1);
        const float px = xn * sc, py = yn * sc, pz = zn * sc;

        float fx = floorf(px), fy = floorf(py), fz = floorf(pz);
        const float hi = (float)(res - 2);
        fx = fminf(fmaxf(fx, 0.0f), hi);
        fy = fminf(fmaxf(fy, 0.0f), hi);
        fz = fminf(fmaxf(fz, 0.0f), hi);

        const float wx = px - fx, wy = py - fy, wz = pz - fz;
        const uint32_t ix0 = (uint32_t)fx, iy0 = (uint32_t)fy, iz0 = (uint32_t)fz;

        float a0, a1;

        if (l < 8) {
            // dense: one LDG.256 fetches the whole fp16 corner cube
            const uint32_t r2 = (uint32_t)(res * res);
            const U8 cu = ldg256u(&g_cube[off + ix0 * r2 + iy0 * (uint32_t)res + iz0]);

            const float wx0 = 1.0f - wx, wy0 = 1.0f - wy, wz0 = 1.0f - wz;
            a0 = 0.0f; a1 = 0.0f;
#pragma unroll
            for (int c = 0; c < 8; ++c) {
                const float w = (((c >> 2) & 1) ? wx : wx0) *
                                (((c >> 1) & 1) ? wy : wy0) *
                                ((c & 1)        ? wz : wz0);
                const float2 f = u32_to_f2(cu.v[c]);
                a0 = fmaf(w, f.x, a0);
                a1 = fmaf(w, f.y, a1);
            }
        } else {
            // hashed: fp16 quads; even ix0 -> both x-corners in one quad
            const uint32_t mask = 0x7FFFFu;                       // size 2^19 for all hashed levels
            const uint4* hq = g_hquad + ((uint32_t)(off - HASHED_BASE) >> 2);
            const bool even = (ix0 & 1u) == 0u;

            const uint32_t hy0 = iy0 * 2654435761u;
            const uint32_t hy1 = hy0 + 2654435761u;
            const uint32_t hz0 = iz0 * 805459861u;
            const uint32_t hz1 = hz0 + 805459861u;
            const uint32_t hh[4] = {hy0 ^ hz0, hy0 ^ hz1, hy1 ^ hz0, hy1 ^ hz1};

            uint32_t jc0[4];
#pragma unroll
            for (int c = 0; c < 4; ++c)
                jc0[c] = (ix0 ^ hh[c]) & mask;

            uint4 q0[4];
#pragma unroll
            for (int c = 0; c < 4; ++c)
                q0[c] = __ldg(hq + (jc0[c] >> 2));

            const float wy0f = 1.0f - wy, wz0f = 1.0f - wz;
            const float wyz[4] = {wy0f * wz0f, wy0f * wz, wy * wz0f, wy * wz};

            a0 = 0.0f; a1 = 0.0f;
#pragma unroll
            for (int c = 0; c < 4; ++c) {
                const uint32_t s0 = jc0[c] & 3u;
                const float2 f0 = u32_to_f2(sel4(q0[c], s0));
                float2 f1;
                if (even) {            // partner differs only in bit 0 -> same quad
                    f1 = u32_to_f2(sel4(q0[c], s0 ^ 1u));
                } else {               // predicated extra quad load (~half the lanes)
                    const uint32_t j1 = ((ix0 + 1u) ^ hh[c]) & mask;
                    const uint4 q1 = __ldg(hq + (j1 >> 2));
                    f1 = u32_to_f2(sel4(q1, j1 & 3u));
                }
                const float g0 = fmaf(wx, f1.x - f0.x, f0.x);
                const float g1 = fmaf(wx, f1.y - f0.y, f0.y);
                a0 = fmaf(wyz[c], g0, a0);
                a1 = fmaf(wyz[c], g1, a1);
            }
        }

        buf[(l & 3) * 2 + 0] = a0;
        buf[(l & 3) * 2 + 1] = a1;
        if ((l & 3) == 3)
            stg256(obase + (l >> 2) * 8, buf);   // one STG.256 per 4 levels
    }
}

extern "C" void kernel_launch(void* const* d_in, const int* in_sizes, int n_in,
                              void* d_out, int out_size)
{
    const float*  xyz = (const float*)d_in[0];
    const float2* emb = (const float2*)d_in[1];
    const float*  mn  = (const float*)d_in[2];
    const float*  mx  = (const float*)d_in[3];
    float* out = (float*)d_out;

    repack_all<<<4096, 256>>>(emb);

    const int threads = 256;
    const int blocks  = BATCH / threads;   // exact
    hashgrid_kernel<<<blocks, threads>>>(xyz, mn, mx, out);
}

// round 16
// speedup vs baseline: 1.5541x; 1.5541x over previous
#include <cuda_runtime.h>
#include <cuda_fp16.h>
#include <stdint.h>
#include <string.h>

#define N_LEVELS 16
#define BATCH (1 << 20)
#define DENSE_TOTAL 1023633          // sum of res^3 for levels 0..7 (== OFFSETS[8])
#define HASHED_BASE 1023633          // first hashed entry
#define HPAIRS 2097152               // (5217937 - 1023633) / 2 pairs

// full 2x2x2 corner cube per dense cell, fp16: 8 corners x half2 = 32 bytes
struct __align__(32) Cube { uint32_t h[8]; };   // h[c] = half2(f0,f1), c = (cx<<2)|(cy<<1)|cz
__device__ Cube g_cube[DENSE_TOTAL];
// hashed pair table (fp32): g_hpair[k] = (emb[HASHED_BASE+2k], emb[HASHED_BASE+2k+1])
__device__ float4 g_hpair[HPAIRS];

__host__ __device__ __forceinline__ constexpr int lvl_res(int l) {
    constexpr int r[N_LEVELS] = {16, 20, 25, 32, 40, 50, 64, 80, 101, 128, 161, 203, 256, 322, 406, 512};
    return r[l];
}
__host__ __device__ __forceinline__ constexpr int lvl_off(int l) {
    constexpr int o[N_LEVELS + 1] = {0, 4096, 12096, 27721, 60489, 124489, 249489, 511633, 1023633,
                                     1547921, 2072209, 2596497, 3120785, 3645073, 4169361, 4693649, 5217937};
    return o[l];
}

// bit-casts (compile to nothing)
__device__ __forceinline__ uint32_t h2_to_u32(__half2 h) {
    uint32_t u; memcpy(&u, &h, 4); return u;
}
__device__ __forceinline__ float2 u32_to_f2(uint32_t u) {
    __half2 h; memcpy(&h, &u, 4); return __half22float2(h);
}

// plain 256-bit global loads (sm_100+)
struct U8 { uint32_t v[8]; };
__device__ __forceinline__ U8 ldg256u(const Cube* p) {
    U8 q;
    asm("ld.global.nc.v8.b32 {%0,%1,%2,%3,%4,%5,%6,%7}, [%8];"
        : "=r"(q.v[0]), "=r"(q.v[1]), "=r"(q.v[2]), "=r"(q.v[3]),
          "=r"(q.v[4]), "=r"(q.v[5]), "=r"(q.v[6]), "=r"(q.v[7])
        : "l"(p));
    return q;
}
// plain 256-bit store
__device__ __forceinline__ void stg256(float* p, const float* v) {
    asm volatile("st.global.v8.f32 [%0], {%1,%2,%3,%4,%5,%6,%7,%8};"
        :: "l"(p), "f"(v[0]), "f"(v[1]), "f"(v[2]), "f"(v[3]),
           "f"(v[4]), "f"(v[5]), "f"(v[6]), "f"(v[7]) : "memory");
}

// ── prologue: build fp16 cube table + fp32 hashed pair table in one launch ─
#define REPACK_ITEMS (DENSE_TOTAL + HPAIRS)
__global__ __launch_bounds__(256) void repack_all(const float2* __restrict__ emb)
{
    for (int t = blockIdx.x * blockDim.x + threadIdx.x; t < REPACK_ITEMS;
         t += gridDim.x * blockDim.x) {
        if (t < DENSE_TOTAL) {
            const int i = t;
            int res = 0;
#pragma unroll
            for (int l = 0; l < 8; ++l)
                if (i >= lvl_off(l) && i < lvl_off(l + 1)) res = lvl_res(l);
            const int r2 = res * res;
            Cube cu;
#pragma unroll
            for (int c = 0; c < 8; ++c) {
                const int dx = (c >> 2) & 1, dy = (c >> 1) & 1, dz = c & 1;
                // edge cells read garbage neighbors but stay inside emb; never consumed.
                const float2 v = __ldg(emb + i + dx * r2 + dy * res + dz);
                cu.h[c] = h2_to_u32(__floats2half2_rn(v.x, v.y));
            }
            g_cube[i] = cu;
        } else {
            const int k = t - DENSE_TOTAL;
            float2 a = __ldg(emb + HASHED_BASE + 2 * k);
            float2 b = __ldg(emb + HASHED_BASE + 2 * k + 1);
            g_hpair[k] = make_float4(a.x, a.y, b.x, b.y);
        }
    }
}

// ── fused main kernel: all 16 levels per point ─────────────────────────────
__global__ __launch_bounds__(256, 6) void hashgrid_kernel(
    const float* __restrict__ xyz,
    const float* __restrict__ mn,
    const float* __restrict__ mx,
    float* __restrict__ out)
{
    const int b = blockIdx.x * blockDim.x + threadIdx.x;   // grid*block == BATCH exactly

    const float inv_x = 1.0f / (mx[0] - mn[0]);
    const float inv_y = 1.0f / (mx[1] - mn[1]);
    const float inv_z = 1.0f / (mx[2] - mn[2]);
    const float xn = (xyz[3 * b + 0] - mn[0]) * inv_x;
    const float yn = (xyz[3 * b + 1] - mn[1]) * inv_y;
    const float zn = (xyz[3 * b + 2] - mn[2]) * inv_z;

    float* obase = out + (size_t)b * (2 * N_LEVELS);
    float buf[8];   // 4 levels x 2 feats, flushed via one STG.256

#pragma unroll
    for (int l = 0; l < N_LEVELS; ++l) {
        const int res = lvl_res(l);
        const int off = lvl_off(l);

        const float sc = (float)(res - 1);
        const float px = xn * sc, py = yn * sc, pz = zn * sc;

        float fx = floorf(px), fy = floorf(py), fz = floorf(pz);
        const float hi = (float)(res - 2);
        fx = fminf(fmaxf(fx, 0.0f), hi);
        fy = fminf(fmaxf(fy, 0.0f), hi);
        fz = fminf(fmaxf(fz, 0.0f), hi);

        const float wx = px - fx, wy = py - fy, wz = pz - fz;
        const uint32_t ix0 = (uint32_t)fx, iy0 = (uint32_t)fy, iz0 = (uint32_t)fz;

        float a0, a1;

        if (l < 8) {
            // dense: one LDG.256 fetches the whole fp16 corner cube
            const uint32_t r2 = (uint32_t)(res * res);
            const U8 cu = ldg256u(&g_cube[off + ix0 * r2 + iy0 * (uint32_t)res + iz0]);

            const float wx0 = 1.0f - wx, wy0 = 1.0f - wy, wz0 = 1.0f - wz;
            a0 = 0.0f; a1 = 0.0f;
#pragma unroll
            for (int c = 0; c < 8; ++c) {
                const float w = (((c >> 2) & 1) ? wx : wx0) *
                                (((c >> 1) & 1) ? wy : wy0) *
                                ((c & 1)        ? wz : wz0);
                const float2 f = u32_to_f2(cu.v[c]);
                a0 = fmaf(w, f.x, a0);
                a1 = fmaf(w, f.y, a1);
            }
        } else {
            // hashed: x-prime is 1 -> even ix0 pairs both x-corners in one 16B load
            const uint32_t mask = 0x7FFFFu;                       // size 2^19 for all hashed levels
            const float4* hp = g_hpair + ((uint32_t)(off - HASHED_BASE) >> 1);
            const bool even = (ix0 & 1u) == 0u;

            const uint32_t hy0 = iy0 * 2654435761u;
            const uint32_t hy1 = hy0 + 2654435761u;
            const uint32_t hz0 = iz0 * 805459861u;
            const uint32_t hz1 = hz0 + 805459861u;
            const uint32_t hh[4] = {hy0 ^ hz0, hy0 ^ hz1, hy1 ^ hz0, hy1 ^ hz1};

            uint32_t jc0[4], jc1[4];
#pragma unroll
            for (int c = 0; c < 4; ++c) {
                jc0[c] = (ix0 ^ hh[c]) & mask;
                jc1[c] = ((ix0 + 1u) ^ hh[c]) & mask;
            }
            float4 q0[4];
#pragma unroll
            for (int c = 0; c < 4; ++c)
                q0[c] = __ldg(hp + (jc0[c] >> 1));

            const float wy0f = 1.0f - wy, wz0f = 1.0f - wz;
            const float wyz[4] = {wy0f * wz0f, wy0f * wz, wy * wz0f, wy * wz};

            a0 = 0.0f; a1 = 0.0f;
#pragma unroll
            for (int c = 0; c < 4; ++c) {
                const bool o0 = (jc0[c] & 1u) != 0u;
                const float f0x = o0 ? q0[c].z : q0[c].x;
                const float f0y = o0 ? q0[c].w : q0[c].y;
                float f1x, f1y;
                if (even) {            // partner is the other half of the same pair
                    f1x = o0 ? q0[c].x : q0[c].z;
                    f1y = o0 ? q0[c].y : q0[c].w;
                } else {               // predicated extra load (~half the lanes)
                    const float4 q1 = __ldg(hp + (jc1[c] >> 1));
                    const bool o1 = (jc1[c] & 1u) != 0u;
                    f1x = o1 ? q1.z : q1.x;
                    f1y = o1 ? q1.w : q1.y;
                }
                const float g0 = fmaf(wx, f1x - f0x, f0x);
                const float g1 = fmaf(wx, f1y - f0y, f0y);
                a0 = fmaf(wyz[c], g0, a0);
                a1 = fmaf(wyz[c], g1, a1);
            }
        }

        buf[(l & 3) * 2 + 0] = a0;
        buf[(l & 3) * 2 + 1] = a1;
        if ((l & 3) == 3)
            stg256(obase + (l >> 2) * 8, buf);   // one STG.256 per 4 levels
    }
}

extern "C" void kernel_launch(void* const* d_in, const int* in_sizes, int n_in,
                              void* d_out, int out_size)
{
    const float*  xyz = (const float*)d_in[0];
    const float2* emb = (const float2*)d_in[1];
    const float*  mn  = (const float*)d_in[2];
    const float*  mx  = (const float*)d_in[3];
    float* out = (float*)d_out;

    repack_all<<<4096, 256>>>(emb);

    const int threads = 256;
    const int blocks  = BATCH / threads;   // exact
    hashgrid_kernel<<<blocks, threads>>>(xyz, mn, mx, out);
}

// round 17
// speedup vs baseline: 1.5767x; 1.0145x over previous
#include <cuda_runtime.h>
#include <cuda_fp16.h>
#include <stdint.h>
#include <string.h>

#define N_LEVELS 16
#define BATCH (1 << 20)
#define DENSE_TOTAL 1023633          // sum of res^3 for levels 0..7 (== OFFSETS[8])
#define HASHED_BASE 1023633          // first hashed entry
#define HPAIRS 2097152               // (5217937 - 1023633) / 2 pairs

// full 2x2x2 corner cube per dense cell, fp16: 8 corners x half2 = 32 bytes
struct __align__(32) Cube { uint32_t h[8]; };   // h[c] = half2(f0,f1), c = (cx<<2)|(cy<<1)|cz
__device__ Cube g_cube[DENSE_TOTAL];
// hashed pair table (fp32): g_hpair[k] = (emb[HASHED_BASE+2k], emb[HASHED_BASE+2k+1])
__device__ float4 g_hpair[HPAIRS];

__host__ __device__ __forceinline__ constexpr int lvl_res(int l) {
    constexpr int r[N_LEVELS] = {16, 20, 25, 32, 40, 50, 64, 80, 101, 128, 161, 203, 256, 322, 406, 512};
    return r[l];
}
__host__ __device__ __forceinline__ constexpr int lvl_off(int l) {
    constexpr int o[N_LEVELS + 1] = {0, 4096, 12096, 27721, 60489, 124489, 249489, 511633, 1023633,
                                     1547921, 2072209, 2596497, 3120785, 3645073, 4169361, 4693649, 5217937};
    return o[l];
}

// bit-casts (compile to nothing)
__device__ __forceinline__ uint32_t h2_to_u32(__half2 h) {
    uint32_t u; memcpy(&u, &h, 4); return u;
}
__device__ __forceinline__ float2 u32_to_f2(uint32_t u) {
    __half2 h; memcpy(&h, &u, 4); return __half22float2(h);
}

// plain 256-bit global loads (sm_100+)
struct U8 { uint32_t v[8]; };
__device__ __forceinline__ U8 ldg256u(const Cube* p) {
    U8 q;
    asm("ld.global.nc.v8.b32 {%0,%1,%2,%3,%4,%5,%6,%7}, [%8];"
        : "=r"(q.v[0]), "=r"(q.v[1]), "=r"(q.v[2]), "=r"(q.v[3]),
          "=r"(q.v[4]), "=r"(q.v[5]), "=r"(q.v[6]), "=r"(q.v[7])
        : "l"(p));
    return q;
}
// 256-bit STREAMING store (.cs = evict-first, legacy cache-op: no policy path)
__device__ __forceinline__ void stg256_cs(float* p, const float* v) {
    asm volatile("st.global.cs.v8.f32 [%0], {%1,%2,%3,%4,%5,%6,%7,%8};"
        :: "l"(p), "f"(v[0]), "f"(v[1]), "f"(v[2]), "f"(v[3]),
           "f"(v[4]), "f"(v[5]), "f"(v[6]), "f"(v[7]) : "memory");
}

// ── prologue: build fp16 cube table + fp32 hashed pair table in one launch ─
#define REPACK_ITEMS (DENSE_TOTAL + HPAIRS)
__global__ __launch_bounds__(256) void repack_all(const float2* __restrict__ emb)
{
    for (int t = blockIdx.x * blockDim.x + threadIdx.x; t < REPACK_ITEMS;
         t += gridDim.x * blockDim.x) {
        if (t < DENSE_TOTAL) {
            const int i = t;
            int res = 0;
#pragma unroll
            for (int l = 0; l < 8; ++l)
                if (i >= lvl_off(l) && i < lvl_off(l + 1)) res = lvl_res(l);
            const int r2 = res * res;
            Cube cu;
#pragma unroll
            for (int c = 0; c < 8; ++c) {
                const int dx = (c >> 2) & 1, dy = (c >> 1) & 1, dz = c & 1;
                // edge cells read garbage neighbors but stay inside emb; never consumed.
                const float2 v = __ldg(emb + i + dx * r2 + dy * res + dz);
                cu.h[c] = h2_to_u32(__floats2half2_rn(v.x, v.y));
            }
            g_cube[i] = cu;
        } else {
            const int k = t - DENSE_TOTAL;
            float2 a = __ldg(emb + HASHED_BASE + 2 * k);
            float2 b = __ldg(emb + HASHED_BASE + 2 * k + 1);
            g_hpair[k] = make_float4(a.x, a.y, b.x, b.y);
        }
    }
}

// ── fused main kernel: all 16 levels per point ─────────────────────────────
__global__ __launch_bounds__(256) void hashgrid_kernel(
    const float* __restrict__ xyz,
    const float* __restrict__ mn,
    const float* __restrict__ mx,
    float* __restrict__ out)
{
    const int b = blockIdx.x * blockDim.x + threadIdx.x;   // grid*block == BATCH exactly

    const float inv_x = 1.0f / (mx[0] - mn[0]);
    const float inv_y = 1.0f / (mx[1] - mn[1]);
    const float inv_z = 1.0f / (mx[2] - mn[2]);
    const float xn = (xyz[3 * b + 0] - mn[0]) * inv_x;
    const float yn = (xyz[3 * b + 1] - mn[1]) * inv_y;
    const float zn = (xyz[3 * b + 2] - mn[2]) * inv_z;

    float* obase = out + (size_t)b * (2 * N_LEVELS);
    float buf[8];   // 4 levels x 2 feats, flushed via one streaming STG.256

#pragma unroll
    for (int l = 0; l < N_LEVELS; ++l) {
        const int res = lvl_res(l);
        const int off = lvl_off(l);

        const float sc = (float)(res - 1);
        const float px = xn * sc, py = yn * sc, pz = zn * sc;

        float fx = floorf(px), fy = floorf(py), fz = floorf(pz);
        const float hi = (float)(res - 2);
        fx = fminf(fmaxf(fx, 0.0f), hi);
        fy = fminf(fmaxf(fy, 0.0f), hi);
        fz = fminf(fmaxf(fz, 0.0f), hi);

        const float wx = px - fx, wy = py - fy, wz = pz - fz;
        const uint32_t ix0 = (uint32_t)fx, iy0 = (uint32_t)fy, iz0 = (uint32_t)fz;

        float a0, a1;

        if (l < 8) {
            // dense: one LDG.256 fetches the whole fp16 corner cube
            const uint32_t r2 = (uint32_t)(res * res);
            const U8 cu = ldg256u(&g_cube[off + ix0 * r2 + iy0 * (uint32_t)res + iz0]);

            const float wx0 = 1.0f - wx, wy0 = 1.0f - wy, wz0 = 1.0f - wz;
            a0 = 0.0f; a1 = 0.0f;
#pragma unroll
            for (int c = 0; c < 8; ++c) {
                const float w = (((c >> 2) & 1) ? wx : wx0) *
                                (((c >> 1) & 1) ? wy : wy0) *
                                ((c & 1)        ? wz : wz0);
                const float2 f = u32_to_f2(cu.v[c]);
                a0 = fmaf(w, f.x, a0);
                a1 = fmaf(w, f.y, a1);
            }
        } else {
            // hashed: x-prime is 1 -> even ix0 pairs both x-corners in one 16B load
            const uint32_t mask = 0x7FFFFu;                       // size 2^19 for all hashed levels
            const float4* hp = g_hpair + ((uint32_t)(off - HASHED_BASE) >> 1);
            const bool even = (ix0 & 1u) == 0u;

            const uint32_t hy0 = iy0 * 2654435761u;
            const uint32_t hy1 = hy0 + 2654435761u;
            const uint32_t hz0 = iz0 * 805459861u;
            const uint32_t hz1 = hz0 + 805459861u;
            const uint32_t hh[4] = {hy0 ^ hz0, hy0 ^ hz1, hy1 ^ hz0, hy1 ^ hz1};

            uint32_t jc0[4], jc1[4];
#pragma unroll
            for (int c = 0; c < 4; ++c) {
                jc0[c] = (ix0 ^ hh[c]) & mask;
                jc1[c] = ((ix0 + 1u) ^ hh[c]) & mask;
            }
            float4 q0[4];
#pragma unroll
            for (int c = 0; c < 4; ++c)
                q0[c] = __ldg(hp + (jc0[c] >> 1));

            const float wy0f = 1.0f - wy, wz0f = 1.0f - wz;
            const float wyz[4] = {wy0f * wz0f, wy0f * wz, wy * wz0f, wy * wz};

            a0 = 0.0f; a1 = 0.0f;
#pragma unroll
            for (int c = 0; c < 4; ++c) {
                const bool o0 = (jc0[c] & 1u) != 0u;
                const float f0x = o0 ? q0[c].z : q0[c].x;
                const float f0y = o0 ? q0[c].w : q0[c].y;
                float f1x, f1y;
                if (even) {            // partner is the other half of the same pair
                    f1x = o0 ? q0[c].x : q0[c].z;
                    f1y = o0 ? q0[c].y : q0[c].w;
                } else {               // predicated extra load (~half the lanes)
                    const float4 q1 = __ldg(hp + (jc1[c] >> 1));
                    const bool o1 = (jc1[c] & 1u) != 0u;
                    f1x = o1 ? q1.z : q1.x;
                    f1y = o1 ? q1.w : q1.y;
                }
                const float g0 = fmaf(wx, f1x - f0x, f0x);
                const float g1 = fmaf(wx, f1y - f0y, f0y);
                a0 = fmaf(wyz[c], g0, a0);
                a1 = fmaf(wyz[c], g1, a1);
            }
        }

        buf[(l & 3) * 2 + 0] = a0;
        buf[(l & 3) * 2 + 1] = a1;
        if ((l & 3) == 3)
            stg256_cs(obase + (l >> 2) * 8, buf);   // streaming store, one per 4 levels
    }
}

extern "C" void kernel_launch(void* const* d_in, const int* in_sizes, int n_in,
                              void* d_out, int out_size)
{
    const float*  xyz = (const float*)d_in[0];
    const float2* emb = (const float2*)d_in[1];
    const float*  mn  = (const float*)d_in[2];
    const float*  mx  = (const float*)d_in[3];
    float* out = (float*)d_out;

    repack_all<<<4096, 256>>>(emb);

    const int threads = 256;
    const int blocks  = BATCH / threads;   // exact
    hashgrid_kernel<<<blocks, threads>>>(xyz, mn, mx, out);
}